// round 10
// baseline (speedup 1.0000x reference)
#include <cuda_runtime.h>
#include <cuda_bf16.h>
#include <cstdint>

#define HID 256
#define MAX_N 50000
#define MAX_E 800000
#define SCAN_T 1024

// ---------------- scratch (static __device__, no allocs) ----------------
__device__ float g_w[MAX_E];                 // per-edge sigmoid weight
__device__ float g_deg[MAX_N];               // weighted degree (excl. self loop)
__device__ float g_dinv[MAX_N];              // rsqrt(deg+1)
__device__ int   g_cnt[MAX_N];               // per-dst edge count
__device__ int   g_ptr[MAX_N + 1];           // CSR offsets
__device__ int   g_cur[MAX_N];               // scatter cursors
__device__ int   g_esrc[MAX_E];              // dst-grouped edge sources
__device__ float g_enrm[MAX_E];              // dst-grouped edge norms
__device__ float g_x[(size_t)MAX_N * HID];   // h @ Wc

// ---------------- helpers ----------------
__device__ __forceinline__ float tanh_approx(float x) {
    float r;
    asm("tanh.approx.f32 %0, %1;" : "=f"(r) : "f"(x));
    return r;
}
__device__ __forceinline__ float to_tf32(float x) {
    uint32_t u;
    asm("cvt.rna.tf32.f32 %0, %1;" : "=r"(u) : "f"(x));
    return __uint_as_float(u);
}
__device__ __forceinline__ void mma_tf32(float4& c, const uint32_t* a, const uint32_t* b) {
    asm volatile(
        "mma.sync.aligned.m16n8k8.row.col.f32.tf32.tf32.f32 "
        "{%0,%1,%2,%3},{%4,%5,%6,%7},{%8,%9},{%0,%1,%2,%3};"
        : "+f"(c.x), "+f"(c.y), "+f"(c.z), "+f"(c.w)
        : "r"(a[0]), "r"(a[1]), "r"(a[2]), "r"(a[3]), "r"(b[0]), "r"(b[1]));
}

// ---------------- kernel 1: TF32 GEMM  x = h @ Wc, reg-staged double buffer ----------------
#define GBM 128
#define GBN 128
#define GBK 32
#define TILESZ (GBK * (GBM + 4))
#define GEMM_SMEM (4 * TILESZ * 4)

__global__ __launch_bounds__(256) void tf32_gemm_kernel(const float* __restrict__ A,
                                                        const float* __restrict__ B,
                                                        float* __restrict__ C, int M) {
    extern __shared__ float sm[];
    float* Asm = sm;
    float* Bsm = sm + 2 * TILESZ;

    int tid = threadIdx.x;
    int wid = tid >> 5;
    int lane = tid & 31;
    int g = lane >> 2;
    int tig = lane & 3;
    int bm = blockIdx.x * GBM;
    int bn = blockIdx.y * GBN;
    int wm = (wid >> 1) * 32;
    int wn = (wid & 1) * 64;
    bool full = (bm + GBM <= M);

    float4 acc[2][8];
#pragma unroll
    for (int mt = 0; mt < 2; mt++)
#pragma unroll
        for (int j = 0; j < 8; j++) acc[mt][j] = make_float4(0.f, 0.f, 0.f, 0.f);

    int arow = tid >> 3;
    int acol4 = tid & 7;
    int brow = tid >> 5;
    int bcol4 = tid & 31;

    float4 ra[4], rb[4];

#define LOAD_TILE(k0)                                                                   \
    {                                                                                   \
        _Pragma("unroll") for (int i = 0; i < 4; i++) {                                 \
            int gr = bm + arow + 32 * i;                                                \
            ra[i] = (full || gr < M)                                                    \
                ? *(const float4*)&A[(size_t)gr * HID + (k0) + acol4 * 4]               \
                : make_float4(0.f, 0.f, 0.f, 0.f);                                      \
        }                                                                               \
        _Pragma("unroll") for (int i = 0; i < 4; i++) {                                 \
            int kk = brow + 8 * i;                                                      \
            rb[i] = *(const float4*)&B[(size_t)((k0) + kk) * HID + bn + bcol4 * 4];     \
        }                                                                               \
    }

#define STORE_TILE(buf)                                                                 \
    {                                                                                   \
        float* ap = Asm + (buf) * TILESZ;                                               \
        float* bp = Bsm + (buf) * TILESZ;                                               \
        _Pragma("unroll") for (int i = 0; i < 4; i++) {                                 \
            int m = arow + 32 * i;                                                      \
            ap[(acol4 * 4 + 0) * (GBM + 4) + m] = to_tf32(ra[i].x);                     \
            ap[(acol4 * 4 + 1) * (GBM + 4) + m] = to_tf32(ra[i].y);                     \
            ap[(acol4 * 4 + 2) * (GBM + 4) + m] = to_tf32(ra[i].z);                     \
            ap[(acol4 * 4 + 3) * (GBM + 4) + m] = to_tf32(ra[i].w);                     \
        }                                                                               \
        _Pragma("unroll") for (int i = 0; i < 4; i++) {                                 \
            int kk = brow + 8 * i;                                                      \
            float4 v = rb[i];                                                           \
            v.x = to_tf32(v.x); v.y = to_tf32(v.y);                                     \
            v.z = to_tf32(v.z); v.w = to_tf32(v.w);                                     \
            *(float4*)&bp[kk * (GBN + 4) + bcol4 * 4] = v;                              \
        }                                                                               \
    }

#define COMPUTE_TILE(buf)                                                               \
    {                                                                                   \
        const float* ap = Asm + (buf) * TILESZ;                                         \
        const float* bp = Bsm + (buf) * TILESZ;                                         \
        _Pragma("unroll") for (int kr = 0; kr < GBK; kr += 8) {                         \
            uint32_t af[2][4];                                                          \
            uint32_t bf[8][2];                                                          \
            _Pragma("unroll") for (int mt = 0; mt < 2; mt++) {                          \
                int mb = wm + mt * 16 + g;                                              \
                af[mt][0] = __float_as_uint(ap[(kr + tig) * (GBM + 4) + mb]);           \
                af[mt][1] = __float_as_uint(ap[(kr + tig) * (GBM + 4) + mb + 8]);       \
                af[mt][2] = __float_as_uint(ap[(kr + tig + 4) * (GBM + 4) + mb]);       \
                af[mt][3] = __float_as_uint(ap[(kr + tig + 4) * (GBM + 4) + mb + 8]);   \
            }                                                                           \
            _Pragma("unroll") for (int j = 0; j < 8; j++) {                             \
                int nb = wn + j * 8 + g;                                                \
                bf[j][0] = __float_as_uint(bp[(kr + tig) * (GBN + 4) + nb]);            \
                bf[j][1] = __float_as_uint(bp[(kr + tig + 4) * (GBN + 4) + nb]);        \
            }                                                                           \
            _Pragma("unroll") for (int mt = 0; mt < 2; mt++)                            \
                _Pragma("unroll") for (int j = 0; j < 8; j++)                           \
                    mma_tf32(acc[mt][j], af[mt], bf[j]);                                \
        }                                                                               \
    }

    LOAD_TILE(0);
    STORE_TILE(0);
    __syncthreads();

    int buf = 0;
#pragma unroll
    for (int t = 1; t < HID / GBK; t++) {
        LOAD_TILE(t * GBK);
        COMPUTE_TILE(buf);
        STORE_TILE(buf ^ 1);
        __syncthreads();
        buf ^= 1;
    }
    COMPUTE_TILE(buf);

#pragma unroll
    for (int mt = 0; mt < 2; mt++) {
        int row0 = bm + wm + mt * 16 + g;
        int row1 = row0 + 8;
#pragma unroll
        for (int j = 0; j < 8; j++) {
            int col = bn + wn + j * 8 + tig * 2;
            if (row0 < M) *(float2*)&C[(size_t)row0 * HID + col] = make_float2(acc[mt][j].x, acc[mt][j].y);
            if (row1 < M) *(float2*)&C[(size_t)row1 * HID + col] = make_float2(acc[mt][j].z, acc[mt][j].w);
        }
    }
#undef LOAD_TILE
#undef STORE_TILE
#undef COMPUTE_TILE
}

// ---------------- kernel 2: zero deg + cnt ----------------
__global__ void zero_kernel(float* __restrict__ deg, int* __restrict__ cnt, int N) {
    int i = blockIdx.x * blockDim.x + threadIdx.x;
    if (i < N) { deg[i] = 0.0f; cnt[i] = 0; }
}

// ---------------- kernel 3: fused edge MLP -> w, + weighted degree + histogram ----------------
__global__ __launch_bounds__(256) void fused_edge_kernel(const float* __restrict__ attr,
                                const float* __restrict__ W1,
                                const float* __restrict__ b1,
                                const float* __restrict__ W2,
                                const float* __restrict__ b2,
                                const int* __restrict__ dst,
                                float* __restrict__ w,
                                float* __restrict__ deg,
                                int* __restrict__ cnt, int E) {
    __shared__ float4 sA[128];
    __shared__ float  sV[128];
    __shared__ float  sAttr[768];
    int tid = threadIdx.x;
    if (tid < 128) {
        sA[tid] = make_float4(W1[tid], W1[128 + tid], W1[256 + tid], b1[tid]);
        sV[tid] = W2[tid];
    }
    long base3 = (long)blockIdx.x * 768;
    if (base3 + 768 <= (long)E * 3) {
        if (tid < 192)
            ((float4*)sAttr)[tid] = ((const float4*)(attr + base3))[tid];
    } else {
        for (int i = tid; i < 768; i += 256) {
            long gi = base3 + i;
            sAttr[i] = (gi < (long)E * 3) ? attr[gi] : 0.0f;
        }
    }
    __syncthreads();
    int e = blockIdx.x * blockDim.x + tid;
    if (e >= E) return;
    float a0 = sAttr[tid * 3 + 0];
    float a1 = sAttr[tid * 3 + 1];
    float a2 = sAttr[tid * 3 + 2];
    float acc = b2[0];
#pragma unroll 8
    for (int j = 0; j < 128; j++) {
        float4 c = sA[j];
        float z = fmaf(a0, c.x, fmaf(a1, c.y, fmaf(a2, c.z, c.w)));
        float t = tanh_approx(0.5f * z);
        acc = fmaf(0.5f * z * (1.0f + t), sV[j], acc);
    }
    float wv = fmaf(0.5f, tanh_approx(0.5f * acc), 0.5f);
    w[e] = wv;
    int c = dst[e];
    atomicAdd(&deg[c], wv);
    atomicAdd(&cnt[c], 1);
}

// ---------------- kernel 4: scan (ptr, cur) + dinv, single block ----------------
__global__ __launch_bounds__(SCAN_T) void scan_dinv_kernel(const int* __restrict__ cnt,
                                                           const float* __restrict__ deg,
                                                           int* __restrict__ ptr,
                                                           int* __restrict__ cur,
                                                           float* __restrict__ dinv, int N) {
    __shared__ int ssum[SCAN_T];
    int tid = threadIdx.x;
    int CH = (N + SCAN_T - 1) / SCAN_T;
    int start = tid * CH;
    int local = 0;
    for (int i = 0; i < CH; i++) {
        int idx = start + i;
        if (idx < N) {
            local += cnt[idx];
            dinv[idx] = rsqrtf(deg[idx] + 1.0f);   // + self loop weight
        }
    }
    ssum[tid] = local;
    __syncthreads();
    for (int off = 1; off < SCAN_T; off <<= 1) {
        int v = (tid >= off) ? ssum[tid - off] : 0;
        __syncthreads();
        ssum[tid] += v;
        __syncthreads();
    }
    int run = ssum[tid] - local;
    for (int i = 0; i < CH; i++) {
        int idx = start + i;
        if (idx < N) {
            ptr[idx] = run;
            cur[idx] = run;
            run += cnt[idx];
        }
    }
    if (tid == SCAN_T - 1) ptr[N] = ssum[SCAN_T - 1];
}

// ---------------- kernel 5: scatter (src, norm) into dst-grouped CSR ----------------
__global__ void scatter_kernel(const int* __restrict__ src,
                               const int* __restrict__ dst,
                               const float* __restrict__ w,
                               const float* __restrict__ dinv,
                               int* __restrict__ cur,
                               int* __restrict__ esrc,
                               float* __restrict__ enrm, int E) {
    int e = blockIdx.x * blockDim.x + threadIdx.x;
    if (e >= E) return;
    int r = src[e];
    int c = dst[e];
    float nrm = w[e] * dinv[r] * dinv[c];
    int pos = atomicAdd(&cur[c], 1);
    esrc[pos] = r;
    enrm[pos] = nrm;
}

// ---------------- kernel 6: ILP-4 pull aggregation (1 warp / node) ----------------
__global__ __launch_bounds__(256) void agg_pull_kernel(const int* __restrict__ ptr,
                                                       const int* __restrict__ esrc,
                                                       const float* __restrict__ enrm,
                                                       const float* __restrict__ dinv,
                                                       const float* __restrict__ x,
                                                       const float* __restrict__ bc,
                                                       float* __restrict__ out, int N) {
    int node = (blockIdx.x * blockDim.x + threadIdx.x) >> 5;
    int lane = threadIdx.x & 31;
    if (node >= N) return;
    const float4* x4 = (const float4*)x;
    const float4* bc4 = (const float4*)bc;
    float4* out4 = (float4*)out;

    float d = dinv[node];
    float s = d * d;                      // self-loop norm
    size_t base = (size_t)node * 64;
    float4 xa = x4[base + lane];
    float4 xb = x4[base + lane + 32];
    float4 ba = bc4[lane];
    float4 bb = bc4[lane + 32];
    float4 acc0, acc1;
    acc0.x = fmaf(s, xa.x, ba.x); acc0.y = fmaf(s, xa.y, ba.y);
    acc0.z = fmaf(s, xa.z, ba.z); acc0.w = fmaf(s, xa.w, ba.w);
    acc1.x = fmaf(s, xb.x, bb.x); acc1.y = fmaf(s, xb.y, bb.y);
    acc1.z = fmaf(s, xb.z, bb.z); acc1.w = fmaf(s, xb.w, bb.w);

    int beg = ptr[node];
    int end = ptr[node + 1];

    for (int i0 = beg; i0 < end; i0 += 32) {
        int m = min(32, end - i0);
        int rl = 0; float nml = 0.0f;
        if (lane < m) { rl = esrc[i0 + lane]; nml = enrm[i0 + lane]; }  // coalesced metadata

        int j = 0;
        for (; j + 4 <= m; j += 4) {
            int rr[4]; float nn[4];
#pragma unroll
            for (int u = 0; u < 4; u++) {
                rr[u] = __shfl_sync(0xffffffffu, rl, j + u);
                nn[u] = __shfl_sync(0xffffffffu, nml, j + u);
            }
            float4 va[4], vb[4];
#pragma unroll
            for (int u = 0; u < 4; u++) {              // 8 independent LDG.128
                const float4* p = x4 + (size_t)rr[u] * 64;
                va[u] = p[lane];
                vb[u] = p[lane + 32];
            }
#pragma unroll
            for (int u = 0; u < 4; u++) {
                float nm = nn[u];
                acc0.x = fmaf(nm, va[u].x, acc0.x); acc0.y = fmaf(nm, va[u].y, acc0.y);
                acc0.z = fmaf(nm, va[u].z, acc0.z); acc0.w = fmaf(nm, va[u].w, acc0.w);
                acc1.x = fmaf(nm, vb[u].x, acc1.x); acc1.y = fmaf(nm, vb[u].y, acc1.y);
                acc1.z = fmaf(nm, vb[u].z, acc1.z); acc1.w = fmaf(nm, vb[u].w, acc1.w);
            }
        }
        for (; j < m; j++) {
            int r = __shfl_sync(0xffffffffu, rl, j);
            float nm = __shfl_sync(0xffffffffu, nml, j);
            const float4* p = x4 + (size_t)r * 64;
            float4 va = p[lane];
            float4 vb = p[lane + 32];
            acc0.x = fmaf(nm, va.x, acc0.x); acc0.y = fmaf(nm, va.y, acc0.y);
            acc0.z = fmaf(nm, va.z, acc0.z); acc0.w = fmaf(nm, va.w, acc0.w);
            acc1.x = fmaf(nm, vb.x, acc1.x); acc1.y = fmaf(nm, vb.y, acc1.y);
            acc1.z = fmaf(nm, vb.z, acc1.z); acc1.w = fmaf(nm, vb.w, acc1.w);
        }
    }
    out4[base + lane] = acc0;
    out4[base + lane + 32] = acc1;
}

// ---------------- launcher ----------------
extern "C" void kernel_launch(void* const* d_in, const int* in_sizes, int n_in,
                              void* d_out, int out_size) {
    const float* h    = (const float*)d_in[0];
    const int*   eidx = (const int*)d_in[1];     // JAX int64 -> int32 (x64 disabled)
    const float* attr = (const float*)d_in[2];
    const float* W1   = (const float*)d_in[3];
    const float* b1   = (const float*)d_in[4];
    const float* W2   = (const float*)d_in[5];
    const float* b2   = (const float*)d_in[6];
    const float* Wc   = (const float*)d_in[7];
    const float* bc   = (const float*)d_in[8];
    float* out = (float*)d_out;

    int N = in_sizes[0] / HID;       // 50000
    int E = in_sizes[2] / 3;         // 800000
    const int* src = eidx;
    const int* dst = eidx + E;

    float* w_dev;    cudaGetSymbolAddress((void**)&w_dev, g_w);
    float* deg_dev;  cudaGetSymbolAddress((void**)&deg_dev, g_deg);
    float* dinv_dev; cudaGetSymbolAddress((void**)&dinv_dev, g_dinv);
    int*   cnt_dev;  cudaGetSymbolAddress((void**)&cnt_dev, g_cnt);
    int*   ptr_dev;  cudaGetSymbolAddress((void**)&ptr_dev, g_ptr);
    int*   cur_dev;  cudaGetSymbolAddress((void**)&cur_dev, g_cur);
    int*   esrc_dev; cudaGetSymbolAddress((void**)&esrc_dev, g_esrc);
    float* enrm_dev; cudaGetSymbolAddress((void**)&enrm_dev, g_enrm);
    float* x_dev;    cudaGetSymbolAddress((void**)&x_dev, g_x);

    static cudaStream_t s_side = nullptr;
    static cudaEvent_t s_fork = nullptr, s_join = nullptr;
    if (!s_side) {
        cudaStreamCreateWithFlags(&s_side, cudaStreamNonBlocking);
        cudaEventCreateWithFlags(&s_fork, cudaEventDisableTiming);
        cudaEventCreateWithFlags(&s_join, cudaEventDisableTiming);
        cudaFuncSetAttribute(tf32_gemm_kernel,
                             cudaFuncAttributeMaxDynamicSharedMemorySize, GEMM_SMEM);
    }

    // fork: GEMM on side stream (pull is the only consumer of x)
    cudaEventRecord(s_fork, 0);
    cudaStreamWaitEvent(s_side, s_fork, 0);
    dim3 ggrid((N + GBM - 1) / GBM, HID / GBN);
    tf32_gemm_kernel<<<ggrid, 256, GEMM_SMEM, s_side>>>(h, Wc, x_dev, N);
    cudaEventRecord(s_join, s_side);

    // main stream: CSR build chain
    zero_kernel<<<(N + 255) / 256, 256>>>(deg_dev, cnt_dev, N);
    fused_edge_kernel<<<(E + 255) / 256, 256>>>(attr, W1, b1, W2, b2, dst, w_dev, deg_dev, cnt_dev, E);
    scan_dinv_kernel<<<1, SCAN_T>>>(cnt_dev, deg_dev, ptr_dev, cur_dev, dinv_dev, N);
    scatter_kernel<<<(E + 255) / 256, 256>>>(src, dst, w_dev, dinv_dev, cur_dev, esrc_dev, enrm_dev, E);

    // join, then pull (needs x)
    cudaStreamWaitEvent(0, s_join, 0);
    agg_pull_kernel<<<(N * 32 + 255) / 256, 256>>>(ptr_dev, esrc_dev, enrm_dev, dinv_dev, x_dev, bc, out, N);
}

// round 12
// speedup vs baseline: 1.5556x; 1.5556x over previous
#include <cuda_runtime.h>
#include <cuda_bf16.h>
#include <cstdint>

#define HID 256
#define MAX_N 50000
#define MAX_E 800000
#define SCB 512                      // elements per scan block

// ---------------- scratch (static __device__, no allocs) ----------------
__device__ float g_w[MAX_E];                 // per-edge sigmoid weight
__device__ float g_deg[MAX_N];               // weighted degree (excl. self loop)
__device__ float g_dinv[MAX_N];              // rsqrt(deg+1)
__device__ int   g_cnt[MAX_N];               // per-dst edge count
__device__ int   g_ptr[MAX_N + 1];           // CSR offsets
__device__ int   g_cur[MAX_N];               // scatter cursors
__device__ int   g_bsum[256];                // scan block sums (+ total)
__device__ int   g_esrc[MAX_E];              // dst-grouped edge sources
__device__ float g_enrm[MAX_E];              // dst-grouped edge norms
__device__ float g_x[(size_t)MAX_N * HID];   // h @ Wc

// ---------------- helpers ----------------
__device__ __forceinline__ float tanh_approx(float x) {
    float r;
    asm("tanh.approx.f32 %0, %1;" : "=f"(r) : "f"(x));
    return r;
}
__device__ __forceinline__ float to_tf32(float x) {
    uint32_t u;
    asm("cvt.rna.tf32.f32 %0, %1;" : "=r"(u) : "f"(x));
    return __uint_as_float(u);
}
__device__ __forceinline__ void mma_tf32(float4& c, const uint32_t* a, const uint32_t* b) {
    asm volatile(
        "mma.sync.aligned.m16n8k8.row.col.f32.tf32.tf32.f32 "
        "{%0,%1,%2,%3},{%4,%5,%6,%7},{%8,%9},{%0,%1,%2,%3};"
        : "+f"(c.x), "+f"(c.y), "+f"(c.z), "+f"(c.w)
        : "r"(a[0]), "r"(a[1]), "r"(a[2]), "r"(a[3]), "r"(b[0]), "r"(b[1]));
}

// ---------------- kernel 1: TF32 GEMM  x = h @ Wc, reg-staged double buffer ----------------
#define GBM 128
#define GBN 128
#define GBK 32
#define TILESZ (GBK * (GBM + 4))
#define GEMM_SMEM (4 * TILESZ * 4)

__global__ __launch_bounds__(256) void tf32_gemm_kernel(const float* __restrict__ A,
                                                        const float* __restrict__ B,
                                                        float* __restrict__ C, int M) {
    extern __shared__ float sm[];
    float* Asm = sm;
    float* Bsm = sm + 2 * TILESZ;

    int tid = threadIdx.x;
    int wid = tid >> 5;
    int lane = tid & 31;
    int g = lane >> 2;
    int tig = lane & 3;
    int bm = blockIdx.x * GBM;
    int bn = blockIdx.y * GBN;
    int wm = (wid >> 1) * 32;
    int wn = (wid & 1) * 64;
    bool full = (bm + GBM <= M);

    float4 acc[2][8];
#pragma unroll
    for (int mt = 0; mt < 2; mt++)
#pragma unroll
        for (int j = 0; j < 8; j++) acc[mt][j] = make_float4(0.f, 0.f, 0.f, 0.f);

    int arow = tid >> 3;
    int acol4 = tid & 7;
    int brow = tid >> 5;
    int bcol4 = tid & 31;

    float4 ra[4], rb[4];

#define LOAD_TILE(k0)                                                                   \
    {                                                                                   \
        _Pragma("unroll") for (int i = 0; i < 4; i++) {                                 \
            int gr = bm + arow + 32 * i;                                                \
            ra[i] = (full || gr < M)                                                    \
                ? *(const float4*)&A[(size_t)gr * HID + (k0) + acol4 * 4]               \
                : make_float4(0.f, 0.f, 0.f, 0.f);                                      \
        }                                                                               \
        _Pragma("unroll") for (int i = 0; i < 4; i++) {                                 \
            int kk = brow + 8 * i;                                                      \
            rb[i] = *(const float4*)&B[(size_t)((k0) + kk) * HID + bn + bcol4 * 4];     \
        }                                                                               \
    }

#define STORE_TILE(buf)                                                                 \
    {                                                                                   \
        float* ap = Asm + (buf) * TILESZ;                                               \
        float* bp = Bsm + (buf) * TILESZ;                                               \
        _Pragma("unroll") for (int i = 0; i < 4; i++) {                                 \
            int m = arow + 32 * i;                                                      \
            ap[(acol4 * 4 + 0) * (GBM + 4) + m] = to_tf32(ra[i].x);                     \
            ap[(acol4 * 4 + 1) * (GBM + 4) + m] = to_tf32(ra[i].y);                     \
            ap[(acol4 * 4 + 2) * (GBM + 4) + m] = to_tf32(ra[i].z);                     \
            ap[(acol4 * 4 + 3) * (GBM + 4) + m] = to_tf32(ra[i].w);                     \
        }                                                                               \
        _Pragma("unroll") for (int i = 0; i < 4; i++) {                                 \
            int kk = brow + 8 * i;                                                      \
            float4 v = rb[i];                                                           \
            v.x = to_tf32(v.x); v.y = to_tf32(v.y);                                     \
            v.z = to_tf32(v.z); v.w = to_tf32(v.w);                                     \
            *(float4*)&bp[kk * (GBN + 4) + bcol4 * 4] = v;                              \
        }                                                                               \
    }

#define COMPUTE_TILE(buf)                                                               \
    {                                                                                   \
        const float* ap = Asm + (buf) * TILESZ;                                         \
        const float* bp = Bsm + (buf) * TILESZ;                                         \
        _Pragma("unroll") for (int kr = 0; kr < GBK; kr += 8) {                         \
            uint32_t af[2][4];                                                          \
            uint32_t bf[8][2];                                                          \
            _Pragma("unroll") for (int mt = 0; mt < 2; mt++) {                          \
                int mb = wm + mt * 16 + g;                                              \
                af[mt][0] = __float_as_uint(ap[(kr + tig) * (GBM + 4) + mb]);           \
                af[mt][1] = __float_as_uint(ap[(kr + tig) * (GBM + 4) + mb + 8]);       \
                af[mt][2] = __float_as_uint(ap[(kr + tig + 4) * (GBM + 4) + mb]);       \
                af[mt][3] = __float_as_uint(ap[(kr + tig + 4) * (GBM + 4) + mb + 8]);   \
            }                                                                           \
            _Pragma("unroll") for (int j = 0; j < 8; j++) {                             \
                int nb = wn + j * 8 + g;                                                \
                bf[j][0] = __float_as_uint(bp[(kr + tig) * (GBN + 4) + nb]);            \
                bf[j][1] = __float_as_uint(bp[(kr + tig + 4) * (GBN + 4) + nb]);        \
            }                                                                           \
            _Pragma("unroll") for (int mt = 0; mt < 2; mt++)                            \
                _Pragma("unroll") for (int j = 0; j < 8; j++)                           \
                    mma_tf32(acc[mt][j], af[mt], bf[j]);                                \
        }                                                                               \
    }

    LOAD_TILE(0);
    STORE_TILE(0);
    __syncthreads();

    int buf = 0;
#pragma unroll
    for (int t = 1; t < HID / GBK; t++) {
        LOAD_TILE(t * GBK);
        COMPUTE_TILE(buf);
        STORE_TILE(buf ^ 1);
        __syncthreads();
        buf ^= 1;
    }
    COMPUTE_TILE(buf);

#pragma unroll
    for (int mt = 0; mt < 2; mt++) {
        int row0 = bm + wm + mt * 16 + g;
        int row1 = row0 + 8;
#pragma unroll
        for (int j = 0; j < 8; j++) {
            int col = bn + wn + j * 8 + tig * 2;
            if (row0 < M) *(float2*)&C[(size_t)row0 * HID + col] = make_float2(acc[mt][j].x, acc[mt][j].y);
            if (row1 < M) *(float2*)&C[(size_t)row1 * HID + col] = make_float2(acc[mt][j].z, acc[mt][j].w);
        }
    }
#undef LOAD_TILE
#undef STORE_TILE
#undef COMPUTE_TILE
}

// ---------------- kernel 2: zero deg + cnt ----------------
__global__ void zero_kernel(float* __restrict__ deg, int* __restrict__ cnt, int N) {
    int i = blockIdx.x * blockDim.x + threadIdx.x;
    if (i < N) { deg[i] = 0.0f; cnt[i] = 0; }
}

// ---------------- kernel 3: fused edge MLP -> w, + weighted degree + histogram ----------------
__global__ __launch_bounds__(256) void fused_edge_kernel(const float* __restrict__ attr,
                                const float* __restrict__ W1,
                                const float* __restrict__ b1,
                                const float* __restrict__ W2,
                                const float* __restrict__ b2,
                                const int* __restrict__ dst,
                                float* __restrict__ w,
                                float* __restrict__ deg,
                                int* __restrict__ cnt, int E) {
    __shared__ float4 sA[128];
    __shared__ float  sV[128];
    __shared__ float  sAttr[768];
    int tid = threadIdx.x;
    if (tid < 128) {
        sA[tid] = make_float4(W1[tid], W1[128 + tid], W1[256 + tid], b1[tid]);
        sV[tid] = W2[tid];
    }
    long base3 = (long)blockIdx.x * 768;
    if (base3 + 768 <= (long)E * 3) {
        if (tid < 192)
            ((float4*)sAttr)[tid] = ((const float4*)(attr + base3))[tid];
    } else {
        for (int i = tid; i < 768; i += 256) {
            long gi = base3 + i;
            sAttr[i] = (gi < (long)E * 3) ? attr[gi] : 0.0f;
        }
    }
    __syncthreads();
    int e = blockIdx.x * blockDim.x + tid;
    if (e >= E) return;
    float a0 = sAttr[tid * 3 + 0];
    float a1 = sAttr[tid * 3 + 1];
    float a2 = sAttr[tid * 3 + 2];
    float acc = b2[0];
#pragma unroll 8
    for (int j = 0; j < 128; j++) {
        float4 c = sA[j];
        float z = fmaf(a0, c.x, fmaf(a1, c.y, fmaf(a2, c.z, c.w)));
        float t = tanh_approx(0.5f * z);
        acc = fmaf(0.5f * z * (1.0f + t), sV[j], acc);
    }
    float wv = fmaf(0.5f, tanh_approx(0.5f * acc), 0.5f);
    w[e] = wv;
    int c = dst[e];
    atomicAdd(&deg[c], wv);
    atomicAdd(&cnt[c], 1);
}

// ---------------- kernels 4a/4b/4c: 3-phase device-wide exclusive scan ----------------
__global__ __launch_bounds__(256) void scan_bsum_kernel(const int* __restrict__ cnt,
                                                        int* __restrict__ bsum, int N) {
    __shared__ int s[256];
    int t = threadIdx.x;
    int base = blockIdx.x * SCB;
    int v = 0;
    int i0 = base + t, i1 = base + t + 256;
    if (i0 < N) v += cnt[i0];
    if (i1 < N) v += cnt[i1];
    s[t] = v;
    __syncthreads();
#pragma unroll
    for (int off = 128; off > 0; off >>= 1) {
        if (t < off) s[t] += s[t + off];
        __syncthreads();
    }
    if (t == 0) bsum[blockIdx.x] = s[0];
}

__global__ __launch_bounds__(128) void scan_mid_kernel(int* __restrict__ bsum, int nb) {
    __shared__ int s[128];
    int t = threadIdx.x;
    int v = (t < nb) ? bsum[t] : 0;
    s[t] = v;
    __syncthreads();
#pragma unroll
    for (int off = 1; off < 128; off <<= 1) {
        int u = (t >= off) ? s[t - off] : 0;
        __syncthreads();
        s[t] += u;
        __syncthreads();
    }
    if (t < nb) bsum[t] = s[t] - v;     // exclusive
    if (t == 127) bsum[nb] = s[127];    // total
}

__global__ __launch_bounds__(256) void scan_final_kernel(const int* __restrict__ cnt,
                                                         const int* __restrict__ bsum,
                                                         const float* __restrict__ deg,
                                                         int* __restrict__ ptr,
                                                         int* __restrict__ cur,
                                                         float* __restrict__ dinv,
                                                         int N, int nb) {
    __shared__ int s[256];
    int t = threadIdx.x;
    int base = blockIdx.x * SCB;
    int i0 = base + 2 * t, i1 = i0 + 1;
    int p0 = (i0 < N) ? cnt[i0] : 0;
    int p1 = (i1 < N) ? cnt[i1] : 0;
    int pair = p0 + p1;
    s[t] = pair;
    __syncthreads();
#pragma unroll
    for (int off = 1; off < 256; off <<= 1) {
        int u = (t >= off) ? s[t - off] : 0;
        __syncthreads();
        s[t] += u;
        __syncthreads();
    }
    int excl = s[t] - pair + bsum[blockIdx.x];
    if (i0 < N) {
        ptr[i0] = excl; cur[i0] = excl;
        dinv[i0] = rsqrtf(deg[i0] + 1.0f);   // + self loop weight
    }
    if (i1 < N) {
        ptr[i1] = excl + p0; cur[i1] = excl + p0;
        dinv[i1] = rsqrtf(deg[i1] + 1.0f);
    }
    if (blockIdx.x == 0 && t == 0) ptr[N] = bsum[nb];
}

// ---------------- kernel 5: scatter (src, norm) into dst-grouped CSR ----------------
__global__ void scatter_kernel(const int* __restrict__ src,
                               const int* __restrict__ dst,
                               const float* __restrict__ w,
                               const float* __restrict__ dinv,
                               int* __restrict__ cur,
                               int* __restrict__ esrc,
                               float* __restrict__ enrm, int E) {
    int e = blockIdx.x * blockDim.x + threadIdx.x;
    if (e >= E) return;
    int r = src[e];
    int c = dst[e];
    float nrm = w[e] * dinv[r] * dinv[c];
    int pos = atomicAdd(&cur[c], 1);
    esrc[pos] = r;
    enrm[pos] = nrm;
}

// ---------------- kernel 6: ILP-4 pull aggregation (1 warp / node) ----------------
__global__ __launch_bounds__(256) void agg_pull_kernel(const int* __restrict__ ptr,
                                                       const int* __restrict__ esrc,
                                                       const float* __restrict__ enrm,
                                                       const float* __restrict__ dinv,
                                                       const float* __restrict__ x,
                                                       const float* __restrict__ bc,
                                                       float* __restrict__ out, int N) {
    int node = (blockIdx.x * blockDim.x + threadIdx.x) >> 5;
    int lane = threadIdx.x & 31;
    if (node >= N) return;
    const float4* x4 = (const float4*)x;
    const float4* bc4 = (const float4*)bc;
    float4* out4 = (float4*)out;

    float d = dinv[node];
    float s = d * d;                      // self-loop norm
    size_t base = (size_t)node * 64;
    float4 xa = x4[base + lane];
    float4 xb = x4[base + lane + 32];
    float4 ba = bc4[lane];
    float4 bb = bc4[lane + 32];
    float4 acc0, acc1;
    acc0.x = fmaf(s, xa.x, ba.x); acc0.y = fmaf(s, xa.y, ba.y);
    acc0.z = fmaf(s, xa.z, ba.z); acc0.w = fmaf(s, xa.w, ba.w);
    acc1.x = fmaf(s, xb.x, bb.x); acc1.y = fmaf(s, xb.y, bb.y);
    acc1.z = fmaf(s, xb.z, bb.z); acc1.w = fmaf(s, xb.w, bb.w);

    int beg = ptr[node];
    int end = ptr[node + 1];

    for (int i0 = beg; i0 < end; i0 += 32) {
        int m = min(32, end - i0);
        int rl = 0; float nml = 0.0f;
        if (lane < m) { rl = esrc[i0 + lane]; nml = enrm[i0 + lane]; }  // coalesced metadata

        int j = 0;
        for (; j + 4 <= m; j += 4) {
            int rr[4]; float nn[4];
#pragma unroll
            for (int u = 0; u < 4; u++) {
                rr[u] = __shfl_sync(0xffffffffu, rl, j + u);
                nn[u] = __shfl_sync(0xffffffffu, nml, j + u);
            }
            float4 va[4], vb[4];
#pragma unroll
            for (int u = 0; u < 4; u++) {              // 8 independent LDG.128
                const float4* p = x4 + (size_t)rr[u] * 64;
                va[u] = p[lane];
                vb[u] = p[lane + 32];
            }
#pragma unroll
            for (int u = 0; u < 4; u++) {
                float nm = nn[u];
                acc0.x = fmaf(nm, va[u].x, acc0.x); acc0.y = fmaf(nm, va[u].y, acc0.y);
                acc0.z = fmaf(nm, va[u].z, acc0.z); acc0.w = fmaf(nm, va[u].w, acc0.w);
                acc1.x = fmaf(nm, vb[u].x, acc1.x); acc1.y = fmaf(nm, vb[u].y, acc1.y);
                acc1.z = fmaf(nm, vb[u].z, acc1.z); acc1.w = fmaf(nm, vb[u].w, acc1.w);
            }
        }
        for (; j < m; j++) {
            int r = __shfl_sync(0xffffffffu, rl, j);
            float nm = __shfl_sync(0xffffffffu, nml, j);
            const float4* p = x4 + (size_t)r * 64;
            float4 va = p[lane];
            float4 vb = p[lane + 32];
            acc0.x = fmaf(nm, va.x, acc0.x); acc0.y = fmaf(nm, va.y, acc0.y);
            acc0.z = fmaf(nm, va.z, acc0.z); acc0.w = fmaf(nm, va.w, acc0.w);
            acc1.x = fmaf(nm, vb.x, acc1.x); acc1.y = fmaf(nm, vb.y, acc1.y);
            acc1.z = fmaf(nm, vb.z, acc1.z); acc1.w = fmaf(nm, vb.w, acc1.w);
        }
    }
    out4[base + lane] = acc0;
    out4[base + lane + 32] = acc1;
}

// ---------------- launcher ----------------
extern "C" void kernel_launch(void* const* d_in, const int* in_sizes, int n_in,
                              void* d_out, int out_size) {
    const float* h    = (const float*)d_in[0];
    const int*   eidx = (const int*)d_in[1];     // JAX int64 -> int32 (x64 disabled)
    const float* attr = (const float*)d_in[2];
    const float* W1   = (const float*)d_in[3];
    const float* b1   = (const float*)d_in[4];
    const float* W2   = (const float*)d_in[5];
    const float* b2   = (const float*)d_in[6];
    const float* Wc   = (const float*)d_in[7];
    const float* bc   = (const float*)d_in[8];
    float* out = (float*)d_out;

    int N = in_sizes[0] / HID;       // 50000
    int E = in_sizes[2] / 3;         // 800000
    const int* src = eidx;
    const int* dst = eidx + E;

    float* w_dev;    cudaGetSymbolAddress((void**)&w_dev, g_w);
    float* deg_dev;  cudaGetSymbolAddress((void**)&deg_dev, g_deg);
    float* dinv_dev; cudaGetSymbolAddress((void**)&dinv_dev, g_dinv);
    int*   cnt_dev;  cudaGetSymbolAddress((void**)&cnt_dev, g_cnt);
    int*   ptr_dev;  cudaGetSymbolAddress((void**)&ptr_dev, g_ptr);
    int*   cur_dev;  cudaGetSymbolAddress((void**)&cur_dev, g_cur);
    int*   bsum_dev; cudaGetSymbolAddress((void**)&bsum_dev, g_bsum);
    int*   esrc_dev; cudaGetSymbolAddress((void**)&esrc_dev, g_esrc);
    float* enrm_dev; cudaGetSymbolAddress((void**)&enrm_dev, g_enrm);
    float* x_dev;    cudaGetSymbolAddress((void**)&x_dev, g_x);

    static cudaStream_t s_side = nullptr;
    static cudaEvent_t s_fork = nullptr, s_join = nullptr;
    if (!s_side) {
        cudaStreamCreateWithFlags(&s_side, cudaStreamNonBlocking);
        cudaEventCreateWithFlags(&s_fork, cudaEventDisableTiming);
        cudaEventCreateWithFlags(&s_join, cudaEventDisableTiming);
        cudaFuncSetAttribute(tf32_gemm_kernel,
                             cudaFuncAttributeMaxDynamicSharedMemorySize, GEMM_SMEM);
    }

    int nb = (N + SCB - 1) / SCB;    // 98 scan blocks

    // fork: GEMM on side stream (pull is the only consumer of x)
    cudaEventRecord(s_fork, 0);
    cudaStreamWaitEvent(s_side, s_fork, 0);
    dim3 ggrid((N + GBM - 1) / GBM, HID / GBN);
    tf32_gemm_kernel<<<ggrid, 256, GEMM_SMEM, s_side>>>(h, Wc, x_dev, N);
    cudaEventRecord(s_join, s_side);

    // main stream: CSR build chain
    zero_kernel<<<(N + 255) / 256, 256>>>(deg_dev, cnt_dev, N);
    fused_edge_kernel<<<(E + 255) / 256, 256>>>(attr, W1, b1, W2, b2, dst, w_dev, deg_dev, cnt_dev, E);
    scan_bsum_kernel<<<nb, 256>>>(cnt_dev, bsum_dev, N);
    scan_mid_kernel<<<1, 128>>>(bsum_dev, nb);
    scan_final_kernel<<<nb, 256>>>(cnt_dev, bsum_dev, deg_dev, ptr_dev, cur_dev, dinv_dev, N, nb);
    scatter_kernel<<<(E + 255) / 256, 256>>>(src, dst, w_dev, dinv_dev, cur_dev, esrc_dev, enrm_dev, E);

    // join, then pull (needs x)
    cudaStreamWaitEvent(0, s_join, 0);
    agg_pull_kernel<<<(N * 32 + 255) / 256, 256>>>(ptr_dev, esrc_dev, enrm_dev, dinv_dev, x_dev, bc, out, N);
}

// round 14
// speedup vs baseline: 1.6028x; 1.0304x over previous
#include <cuda_runtime.h>
#include <cuda_fp16.h>
#include <cstdint>

#define HID 256
#define MAX_N 50000
#define MAX_E 800000
#define SCB 512                      // elements per scan block

// ---------------- scratch (static __device__, no allocs) ----------------
__device__ float  g_w[MAX_E];                 // per-edge sigmoid weight
__device__ float  g_deg[MAX_N];               // weighted degree (excl. self loop)
__device__ float  g_dinv[MAX_N];              // rsqrt(deg+1)
__device__ int    g_cnt[MAX_N];               // per-dst edge count
__device__ int    g_ptr[MAX_N + 1];           // CSR offsets
__device__ int    g_cur[MAX_N];               // scatter cursors
__device__ int    g_bsum[256];                // scan block sums (+ total)
__device__ int2   g_epack[MAX_E];             // dst-grouped (src, norm-bits)
__device__ float  g_x[(size_t)MAX_N * HID];   // h @ Wc (fp32)
__device__ __half g_xh[(size_t)MAX_N * HID];  // h @ Wc (fp16 gather copy)

// ---------------- helpers ----------------
__device__ __forceinline__ float tanh_approx(float x) {
    float r;
    asm("tanh.approx.f32 %0, %1;" : "=f"(r) : "f"(x));
    return r;
}
__device__ __forceinline__ float to_tf32(float x) {
    uint32_t u;
    asm("cvt.rna.tf32.f32 %0, %1;" : "=r"(u) : "f"(x));
    return __uint_as_float(u);
}
__device__ __forceinline__ void mma_tf32(float4& c, const uint32_t* a, const uint32_t* b) {
    asm volatile(
        "mma.sync.aligned.m16n8k8.row.col.f32.tf32.tf32.f32 "
        "{%0,%1,%2,%3},{%4,%5,%6,%7},{%8,%9},{%0,%1,%2,%3};"
        : "+f"(c.x), "+f"(c.y), "+f"(c.z), "+f"(c.w)
        : "r"(a[0]), "r"(a[1]), "r"(a[2]), "r"(a[3]), "r"(b[0]), "r"(b[1]));
}

// ---------------- kernel 1: TF32 GEMM  x = h @ Wc (fp32 + fp16 outputs) ----------------
#define GBM 128
#define GBN 128
#define GBK 32
#define TILESZ (GBK * (GBM + 4))
#define GEMM_SMEM (4 * TILESZ * 4)

__global__ __launch_bounds__(256) void tf32_gemm_kernel(const float* __restrict__ A,
                                                        const float* __restrict__ B,
                                                        float* __restrict__ C,
                                                        __half* __restrict__ Ch, int M) {
    extern __shared__ float sm[];
    float* Asm = sm;
    float* Bsm = sm + 2 * TILESZ;

    int tid = threadIdx.x;
    int wid = tid >> 5;
    int lane = tid & 31;
    int g = lane >> 2;
    int tig = lane & 3;
    int bm = blockIdx.x * GBM;
    int bn = blockIdx.y * GBN;
    int wm = (wid >> 1) * 32;
    int wn = (wid & 1) * 64;
    bool full = (bm + GBM <= M);

    float4 acc[2][8];
#pragma unroll
    for (int mt = 0; mt < 2; mt++)
#pragma unroll
        for (int j = 0; j < 8; j++) acc[mt][j] = make_float4(0.f, 0.f, 0.f, 0.f);

    int arow = tid >> 3;
    int acol4 = tid & 7;
    int brow = tid >> 5;
    int bcol4 = tid & 31;

    float4 ra[4], rb[4];

#define LOAD_TILE(k0)                                                                   \
    {                                                                                   \
        _Pragma("unroll") for (int i = 0; i < 4; i++) {                                 \
            int gr = bm + arow + 32 * i;                                                \
            ra[i] = (full || gr < M)                                                    \
                ? *(const float4*)&A[(size_t)gr * HID + (k0) + acol4 * 4]               \
                : make_float4(0.f, 0.f, 0.f, 0.f);                                      \
        }                                                                               \
        _Pragma("unroll") for (int i = 0; i < 4; i++) {                                 \
            int kk = brow + 8 * i;                                                      \
            rb[i] = *(const float4*)&B[(size_t)((k0) + kk) * HID + bn + bcol4 * 4];     \
        }                                                                               \
    }

#define STORE_TILE(buf)                                                                 \
    {                                                                                   \
        float* ap = Asm + (buf) * TILESZ;                                               \
        float* bp = Bsm + (buf) * TILESZ;                                               \
        _Pragma("unroll") for (int i = 0; i < 4; i++) {                                 \
            int m = arow + 32 * i;                                                      \
            ap[(acol4 * 4 + 0) * (GBM + 4) + m] = to_tf32(ra[i].x);                     \
            ap[(acol4 * 4 + 1) * (GBM + 4) + m] = to_tf32(ra[i].y);                     \
            ap[(acol4 * 4 + 2) * (GBM + 4) + m] = to_tf32(ra[i].z);                     \
            ap[(acol4 * 4 + 3) * (GBM + 4) + m] = to_tf32(ra[i].w);                     \
        }                                                                               \
        _Pragma("unroll") for (int i = 0; i < 4; i++) {                                 \
            int kk = brow + 8 * i;                                                      \
            float4 v = rb[i];                                                           \
            v.x = to_tf32(v.x); v.y = to_tf32(v.y);                                     \
            v.z = to_tf32(v.z); v.w = to_tf32(v.w);                                     \
            *(float4*)&bp[kk * (GBN + 4) + bcol4 * 4] = v;                              \
        }                                                                               \
    }

#define COMPUTE_TILE(buf)                                                               \
    {                                                                                   \
        const float* ap = Asm + (buf) * TILESZ;                                         \
        const float* bp = Bsm + (buf) * TILESZ;                                         \
        _Pragma("unroll") for (int kr = 0; kr < GBK; kr += 8) {                         \
            uint32_t af[2][4];                                                          \
            uint32_t bf[8][2];                                                          \
            _Pragma("unroll") for (int mt = 0; mt < 2; mt++) {                          \
                int mb = wm + mt * 16 + g;                                              \
                af[mt][0] = __float_as_uint(ap[(kr + tig) * (GBM + 4) + mb]);           \
                af[mt][1] = __float_as_uint(ap[(kr + tig) * (GBM + 4) + mb + 8]);       \
                af[mt][2] = __float_as_uint(ap[(kr + tig + 4) * (GBM + 4) + mb]);       \
                af[mt][3] = __float_as_uint(ap[(kr + tig + 4) * (GBM + 4) + mb + 8]);   \
            }                                                                           \
            _Pragma("unroll") for (int j = 0; j < 8; j++) {                             \
                int nb = wn + j * 8 + g;                                                \
                bf[j][0] = __float_as_uint(bp[(kr + tig) * (GBN + 4) + nb]);            \
                bf[j][1] = __float_as_uint(bp[(kr + tig + 4) * (GBN + 4) + nb]);        \
            }                                                                           \
            _Pragma("unroll") for (int mt = 0; mt < 2; mt++)                            \
                _Pragma("unroll") for (int j = 0; j < 8; j++)                           \
                    mma_tf32(acc[mt][j], af[mt], bf[j]);                                \
        }                                                                               \
    }

    LOAD_TILE(0);
    STORE_TILE(0);
    __syncthreads();

    int buf = 0;
#pragma unroll
    for (int t = 1; t < HID / GBK; t++) {
        LOAD_TILE(t * GBK);
        COMPUTE_TILE(buf);
        STORE_TILE(buf ^ 1);
        __syncthreads();
        buf ^= 1;
    }
    COMPUTE_TILE(buf);

#pragma unroll
    for (int mt = 0; mt < 2; mt++) {
        int row0 = bm + wm + mt * 16 + g;
        int row1 = row0 + 8;
#pragma unroll
        for (int j = 0; j < 8; j++) {
            int col = bn + wn + j * 8 + tig * 2;
            if (row0 < M) {
                *(float2*)&C[(size_t)row0 * HID + col] = make_float2(acc[mt][j].x, acc[mt][j].y);
                *(__half2*)&Ch[(size_t)row0 * HID + col] = __floats2half2_rn(acc[mt][j].x, acc[mt][j].y);
            }
            if (row1 < M) {
                *(float2*)&C[(size_t)row1 * HID + col] = make_float2(acc[mt][j].z, acc[mt][j].w);
                *(__half2*)&Ch[(size_t)row1 * HID + col] = __floats2half2_rn(acc[mt][j].z, acc[mt][j].w);
            }
        }
    }
#undef LOAD_TILE
#undef STORE_TILE
#undef COMPUTE_TILE
}

// ---------------- kernel 2: zero deg + cnt ----------------
__global__ void zero_kernel(float* __restrict__ deg, int* __restrict__ cnt, int N) {
    int i = blockIdx.x * blockDim.x + threadIdx.x;
    if (i < N) { deg[i] = 0.0f; cnt[i] = 0; }
}

// ---------------- kernel 3: fused edge MLP -> w, + weighted degree + histogram ----------------
__global__ __launch_bounds__(256) void fused_edge_kernel(const float* __restrict__ attr,
                                const float* __restrict__ W1,
                                const float* __restrict__ b1,
                                const float* __restrict__ W2,
                                const float* __restrict__ b2,
                                const int* __restrict__ dst,
                                float* __restrict__ w,
                                float* __restrict__ deg,
                                int* __restrict__ cnt, int E) {
    __shared__ float4 sA[128];
    __shared__ float  sV[128];
    __shared__ float  sAttr[768];
    int tid = threadIdx.x;
    if (tid < 128) {
        sA[tid] = make_float4(W1[tid], W1[128 + tid], W1[256 + tid], b1[tid]);
        sV[tid] = W2[tid];
    }
    long base3 = (long)blockIdx.x * 768;
    if (base3 + 768 <= (long)E * 3) {
        if (tid < 192)
            ((float4*)sAttr)[tid] = ((const float4*)(attr + base3))[tid];
    } else {
        for (int i = tid; i < 768; i += 256) {
            long gi = base3 + i;
            sAttr[i] = (gi < (long)E * 3) ? attr[gi] : 0.0f;
        }
    }
    __syncthreads();
    int e = blockIdx.x * blockDim.x + tid;
    if (e >= E) return;
    float a0 = sAttr[tid * 3 + 0];
    float a1 = sAttr[tid * 3 + 1];
    float a2 = sAttr[tid * 3 + 2];
    float acc = b2[0];
#pragma unroll 8
    for (int j = 0; j < 128; j++) {
        float4 c = sA[j];
        float z = fmaf(a0, c.x, fmaf(a1, c.y, fmaf(a2, c.z, c.w)));
        float t = tanh_approx(0.5f * z);
        acc = fmaf(0.5f * z * (1.0f + t), sV[j], acc);
    }
    float wv = fmaf(0.5f, tanh_approx(0.5f * acc), 0.5f);
    w[e] = wv;
    int c = dst[e];
    atomicAdd(&deg[c], wv);
    atomicAdd(&cnt[c], 1);
}

// ---------------- kernels 4a/4b/4c: 3-phase device-wide exclusive scan ----------------
__global__ __launch_bounds__(256) void scan_bsum_kernel(const int* __restrict__ cnt,
                                                        int* __restrict__ bsum, int N) {
    __shared__ int s[256];
    int t = threadIdx.x;
    int base = blockIdx.x * SCB;
    int v = 0;
    int i0 = base + t, i1 = base + t + 256;
    if (i0 < N) v += cnt[i0];
    if (i1 < N) v += cnt[i1];
    s[t] = v;
    __syncthreads();
#pragma unroll
    for (int off = 128; off > 0; off >>= 1) {
        if (t < off) s[t] += s[t + off];
        __syncthreads();
    }
    if (t == 0) bsum[blockIdx.x] = s[0];
}

__global__ __launch_bounds__(128) void scan_mid_kernel(int* __restrict__ bsum, int nb) {
    __shared__ int s[128];
    int t = threadIdx.x;
    int v = (t < nb) ? bsum[t] : 0;
    s[t] = v;
    __syncthreads();
#pragma unroll
    for (int off = 1; off < 128; off <<= 1) {
        int u = (t >= off) ? s[t - off] : 0;
        __syncthreads();
        s[t] += u;
        __syncthreads();
    }
    if (t < nb) bsum[t] = s[t] - v;     // exclusive
    if (t == 127) bsum[nb] = s[127];    // total
}

__global__ __launch_bounds__(256) void scan_final_kernel(const int* __restrict__ cnt,
                                                         const int* __restrict__ bsum,
                                                         const float* __restrict__ deg,
                                                         int* __restrict__ ptr,
                                                         int* __restrict__ cur,
                                                         float* __restrict__ dinv,
                                                         int N, int nb) {
    __shared__ int s[256];
    int t = threadIdx.x;
    int base = blockIdx.x * SCB;
    int i0 = base + 2 * t, i1 = i0 + 1;
    int p0 = (i0 < N) ? cnt[i0] : 0;
    int p1 = (i1 < N) ? cnt[i1] : 0;
    int pair = p0 + p1;
    s[t] = pair;
    __syncthreads();
#pragma unroll
    for (int off = 1; off < 256; off <<= 1) {
        int u = (t >= off) ? s[t - off] : 0;
        __syncthreads();
        s[t] += u;
        __syncthreads();
    }
    int excl = s[t] - pair + bsum[blockIdx.x];
    if (i0 < N) {
        ptr[i0] = excl; cur[i0] = excl;
        dinv[i0] = rsqrtf(deg[i0] + 1.0f);   // + self loop weight
    }
    if (i1 < N) {
        ptr[i1] = excl + p0; cur[i1] = excl + p0;
        dinv[i1] = rsqrtf(deg[i1] + 1.0f);
    }
    if (blockIdx.x == 0 && t == 0) ptr[N] = bsum[nb];
}

// ---------------- kernel 5: scatter packed (src, norm) into dst-grouped CSR ----------------
__global__ void scatter_kernel(const int* __restrict__ src,
                               const int* __restrict__ dst,
                               const float* __restrict__ w,
                               const float* __restrict__ dinv,
                               int* __restrict__ cur,
                               int2* __restrict__ epack, int E) {
    int e = blockIdx.x * blockDim.x + threadIdx.x;
    if (e >= E) return;
    int r = src[e];
    int c = dst[e];
    float nrm = w[e] * dinv[r] * dinv[c];
    int pos = atomicAdd(&cur[c], 1);
    epack[pos] = make_int2(r, __float_as_int(nrm));   // single STG.64
}

// ---------------- kernel 6: ILP-4 fp16-gather pull aggregation (1 warp / node) ----------------
// Lane l owns columns [8l, 8l+8): one uint4 of halves per gathered row.
__global__ __launch_bounds__(256) void agg_pull_kernel(const int* __restrict__ ptr,
                                                       const int2* __restrict__ epack,
                                                       const float* __restrict__ dinv,
                                                       const float* __restrict__ x,
                                                       const __half* __restrict__ xh,
                                                       const float* __restrict__ bc,
                                                       float* __restrict__ out, int N) {
    int node = (blockIdx.x * blockDim.x + threadIdx.x) >> 5;
    int lane = threadIdx.x & 31;
    if (node >= N) return;
    const float4* x4 = (const float4*)x;
    const uint4* xh4 = (const uint4*)xh;      // 32 uint4 per row (256 halves)
    const float4* bc4 = (const float4*)bc;
    float4* out4 = (float4*)out;

    float d = dinv[node];
    float s = d * d;                          // self-loop norm
    size_t base = (size_t)node * 64;          // float4 units
    int c4 = lane * 2;                        // this lane's first float4 chunk
    float4 xa = x4[base + c4];
    float4 xb = x4[base + c4 + 1];
    float4 ba = bc4[c4];
    float4 bb = bc4[c4 + 1];
    float4 acc0, acc1;
    acc0.x = fmaf(s, xa.x, ba.x); acc0.y = fmaf(s, xa.y, ba.y);
    acc0.z = fmaf(s, xa.z, ba.z); acc0.w = fmaf(s, xa.w, ba.w);
    acc1.x = fmaf(s, xb.x, bb.x); acc1.y = fmaf(s, xb.y, bb.y);
    acc1.z = fmaf(s, xb.z, bb.z); acc1.w = fmaf(s, xb.w, bb.w);

    int beg = ptr[node];
    int end = ptr[node + 1];

    for (int i0 = beg; i0 < end; i0 += 32) {
        int m = min(32, end - i0);
        int rl = 0; float nml = 0.0f;
        if (lane < m) {
            int2 pk = epack[i0 + lane];       // coalesced 8B metadata
            rl = pk.x; nml = __int_as_float(pk.y);
        }

        int j = 0;
        for (; j + 4 <= m; j += 4) {
            int rr[4]; float nn[4];
#pragma unroll
            for (int u = 0; u < 4; u++) {
                rr[u] = __shfl_sync(0xffffffffu, rl, j + u);
                nn[u] = __shfl_sync(0xffffffffu, nml, j + u);
            }
            uint4 hv[4];
#pragma unroll
            for (int u = 0; u < 4; u++)                   // 4 independent LDG.128
                hv[u] = xh4[(size_t)rr[u] * 32 + lane];
#pragma unroll
            for (int u = 0; u < 4; u++) {
                float nm = nn[u];
                const __half2* hp = (const __half2*)&hv[u];
                float2 f0 = __half22float2(hp[0]);
                float2 f1 = __half22float2(hp[1]);
                float2 f2 = __half22float2(hp[2]);
                float2 f3 = __half22float2(hp[3]);
                acc0.x = fmaf(nm, f0.x, acc0.x); acc0.y = fmaf(nm, f0.y, acc0.y);
                acc0.z = fmaf(nm, f1.x, acc0.z); acc0.w = fmaf(nm, f1.y, acc0.w);
                acc1.x = fmaf(nm, f2.x, acc1.x); acc1.y = fmaf(nm, f2.y, acc1.y);
                acc1.z = fmaf(nm, f3.x, acc1.z); acc1.w = fmaf(nm, f3.y, acc1.w);
            }
        }
        for (; j < m; j++) {
            int r = __shfl_sync(0xffffffffu, rl, j);
            float nm = __shfl_sync(0xffffffffu, nml, j);
            uint4 hv = xh4[(size_t)r * 32 + lane];
            const __half2* hp = (const __half2*)&hv;
            float2 f0 = __half22float2(hp[0]);
            float2 f1 = __half22float2(hp[1]);
            float2 f2 = __half22float2(hp[2]);
            float2 f3 = __half22float2(hp[3]);
            acc0.x = fmaf(nm, f0.x, acc0.x); acc0.y = fmaf(nm, f0.y, acc0.y);
            acc0.z = fmaf(nm, f1.x, acc0.z); acc0.w = fmaf(nm, f1.y, acc0.w);
            acc1.x = fmaf(nm, f2.x, acc1.x); acc1.y = fmaf(nm, f2.y, acc1.y);
            acc1.z = fmaf(nm, f3.x, acc1.z); acc1.w = fmaf(nm, f3.y, acc1.w);
        }
    }
    out4[base + c4] = acc0;
    out4[base + c4 + 1] = acc1;
}

// ---------------- launcher ----------------
extern "C" void kernel_launch(void* const* d_in, const int* in_sizes, int n_in,
                              void* d_out, int out_size) {
    const float* h    = (const float*)d_in[0];
    const int*   eidx = (const int*)d_in[1];     // JAX int64 -> int32 (x64 disabled)
    const float* attr = (const float*)d_in[2];
    const float* W1   = (const float*)d_in[3];
    const float* b1   = (const float*)d_in[4];
    const float* W2   = (const float*)d_in[5];
    const float* b2   = (const float*)d_in[6];
    const float* Wc   = (const float*)d_in[7];
    const float* bc   = (const float*)d_in[8];
    float* out = (float*)d_out;

    int N = in_sizes[0] / HID;       // 50000
    int E = in_sizes[2] / 3;         // 800000
    const int* src = eidx;
    const int* dst = eidx + E;

    float*  w_dev;    cudaGetSymbolAddress((void**)&w_dev, g_w);
    float*  deg_dev;  cudaGetSymbolAddress((void**)&deg_dev, g_deg);
    float*  dinv_dev; cudaGetSymbolAddress((void**)&dinv_dev, g_dinv);
    int*    cnt_dev;  cudaGetSymbolAddress((void**)&cnt_dev, g_cnt);
    int*    ptr_dev;  cudaGetSymbolAddress((void**)&ptr_dev, g_ptr);
    int*    cur_dev;  cudaGetSymbolAddress((void**)&cur_dev, g_cur);
    int*    bsum_dev; cudaGetSymbolAddress((void**)&bsum_dev, g_bsum);
    int2*   epack_dev; cudaGetSymbolAddress((void**)&epack_dev, g_epack);
    float*  x_dev;    cudaGetSymbolAddress((void**)&x_dev, g_x);
    __half* xh_dev;   cudaGetSymbolAddress((void**)&xh_dev, g_xh);

    static cudaStream_t s_side = nullptr;
    static cudaEvent_t s_fork = nullptr, s_join = nullptr;
    if (!s_side) {
        cudaStreamCreateWithFlags(&s_side, cudaStreamNonBlocking);
        cudaEventCreateWithFlags(&s_fork, cudaEventDisableTiming);
        cudaEventCreateWithFlags(&s_join, cudaEventDisableTiming);
        cudaFuncSetAttribute(tf32_gemm_kernel,
                             cudaFuncAttributeMaxDynamicSharedMemorySize, GEMM_SMEM);
    }

    int nb = (N + SCB - 1) / SCB;    // 98 scan blocks

    // fork: GEMM on side stream (pull is the only consumer of x/xh)
    cudaEventRecord(s_fork, 0);
    cudaStreamWaitEvent(s_side, s_fork, 0);
    dim3 ggrid((N + GBM - 1) / GBM, HID / GBN);
    tf32_gemm_kernel<<<ggrid, 256, GEMM_SMEM, s_side>>>(h, Wc, x_dev, xh_dev, N);
    cudaEventRecord(s_join, s_side);

    // main stream: CSR build chain
    zero_kernel<<<(N + 255) / 256, 256>>>(deg_dev, cnt_dev, N);
    fused_edge_kernel<<<(E + 255) / 256, 256>>>(attr, W1, b1, W2, b2, dst, w_dev, deg_dev, cnt_dev, E);
    scan_bsum_kernel<<<nb, 256>>>(cnt_dev, bsum_dev, N);
    scan_mid_kernel<<<1, 128>>>(bsum_dev, nb);
    scan_final_kernel<<<nb, 256>>>(cnt_dev, bsum_dev, deg_dev, ptr_dev, cur_dev, dinv_dev, N, nb);
    scatter_kernel<<<(E + 255) / 256, 256>>>(src, dst, w_dev, dinv_dev, cur_dev, epack_dev, E);

    // join, then pull (needs x/xh)
    cudaStreamWaitEvent(0, s_join, 0);
    agg_pull_kernel<<<(N * 32 + 255) / 256, 256>>>(ptr_dev, epack_dev, dinv_dev, x_dev, xh_dev, bc, out, N);
}

// round 15
// speedup vs baseline: 1.6976x; 1.0591x over previous
#include <cuda_runtime.h>
#include <cuda_fp16.h>
#include <cstdint>

#define HID 256
#define MAX_N 50000
#define MAX_E 800000
#define SCB 512                      // elements per scan block

// ---------------- scratch (static __device__, no allocs) ----------------
__device__ float  g_w[MAX_E];                 // per-edge sigmoid weight
__device__ float  g_deg[MAX_N];               // weighted degree (excl. self loop)
__device__ float  g_dinv[MAX_N];              // rsqrt(deg+1)
__device__ int    g_cnt[MAX_N];               // per-dst edge count
__device__ int    g_ptr[MAX_N + 1];           // CSR offsets
__device__ int    g_cur[MAX_N];               // scatter cursors
__device__ int    g_bsum[256];                // scan block sums (+ total)
__device__ int2   g_epack[MAX_E];             // dst-grouped (src, norm-bits)
__device__ __half g_xh[(size_t)MAX_N * HID];  // h @ Wc (fp16)

// ---------------- helpers ----------------
__device__ __forceinline__ float tanh_approx(float x) {
    float r;
    asm("tanh.approx.f32 %0, %1;" : "=f"(r) : "f"(x));
    return r;
}
__device__ __forceinline__ float to_tf32(float x) {
    uint32_t u;
    asm("cvt.rna.tf32.f32 %0, %1;" : "=r"(u) : "f"(x));
    return __uint_as_float(u);
}
__device__ __forceinline__ void mma_tf32(float4& c, const uint32_t* a, const uint32_t* b) {
    asm volatile(
        "mma.sync.aligned.m16n8k8.row.col.f32.tf32.tf32.f32 "
        "{%0,%1,%2,%3},{%4,%5,%6,%7},{%8,%9},{%0,%1,%2,%3};"
        : "+f"(c.x), "+f"(c.y), "+f"(c.z), "+f"(c.w)
        : "r"(a[0]), "r"(a[1]), "r"(a[2]), "r"(a[3]), "r"(b[0]), "r"(b[1]));
}

// ---------------- kernel 1: TF32 GEMM  xh = fp16(h @ Wc) ----------------
#define GBM 128
#define GBN 128
#define GBK 32
#define TILESZ (GBK * (GBM + 4))
#define GEMM_SMEM (4 * TILESZ * 4)

__global__ __launch_bounds__(256) void tf32_gemm_kernel(const float* __restrict__ A,
                                                        const float* __restrict__ B,
                                                        __half* __restrict__ Ch, int M) {
    extern __shared__ float sm[];
    float* Asm = sm;
    float* Bsm = sm + 2 * TILESZ;

    int tid = threadIdx.x;
    int wid = tid >> 5;
    int lane = tid & 31;
    int g = lane >> 2;
    int tig = lane & 3;
    int bm = blockIdx.x * GBM;
    int bn = blockIdx.y * GBN;
    int wm = (wid >> 1) * 32;
    int wn = (wid & 1) * 64;
    bool full = (bm + GBM <= M);

    float4 acc[2][8];
#pragma unroll
    for (int mt = 0; mt < 2; mt++)
#pragma unroll
        for (int j = 0; j < 8; j++) acc[mt][j] = make_float4(0.f, 0.f, 0.f, 0.f);

    int arow = tid >> 3;
    int acol4 = tid & 7;
    int brow = tid >> 5;
    int bcol4 = tid & 31;

    float4 ra[4], rb[4];

#define LOAD_TILE(k0)                                                                   \
    {                                                                                   \
        _Pragma("unroll") for (int i = 0; i < 4; i++) {                                 \
            int gr = bm + arow + 32 * i;                                                \
            ra[i] = (full || gr < M)                                                    \
                ? *(const float4*)&A[(size_t)gr * HID + (k0) + acol4 * 4]               \
                : make_float4(0.f, 0.f, 0.f, 0.f);                                      \
        }                                                                               \
        _Pragma("unroll") for (int i = 0; i < 4; i++) {                                 \
            int kk = brow + 8 * i;                                                      \
            rb[i] = *(const float4*)&B[(size_t)((k0) + kk) * HID + bn + bcol4 * 4];     \
        }                                                                               \
    }

#define STORE_TILE(buf)                                                                 \
    {                                                                                   \
        float* ap = Asm + (buf) * TILESZ;                                               \
        float* bp = Bsm + (buf) * TILESZ;                                               \
        _Pragma("unroll") for (int i = 0; i < 4; i++) {                                 \
            int m = arow + 32 * i;                                                      \
            ap[(acol4 * 4 + 0) * (GBM + 4) + m] = to_tf32(ra[i].x);                     \
            ap[(acol4 * 4 + 1) * (GBM + 4) + m] = to_tf32(ra[i].y);                     \
            ap[(acol4 * 4 + 2) * (GBM + 4) + m] = to_tf32(ra[i].z);                     \
            ap[(acol4 * 4 + 3) * (GBM + 4) + m] = to_tf32(ra[i].w);                     \
        }                                                                               \
        _Pragma("unroll") for (int i = 0; i < 4; i++) {                                 \
            int kk = brow + 8 * i;                                                      \
            float4 v = rb[i];                                                           \
            v.x = to_tf32(v.x); v.y = to_tf32(v.y);                                     \
            v.z = to_tf32(v.z); v.w = to_tf32(v.w);                                     \
            *(float4*)&bp[kk * (GBN + 4) + bcol4 * 4] = v;                              \
        }                                                                               \
    }

#define COMPUTE_TILE(buf)                                                               \
    {                                                                                   \
        const float* ap = Asm + (buf) * TILESZ;                                         \
        const float* bp = Bsm + (buf) * TILESZ;                                         \
        _Pragma("unroll") for (int kr = 0; kr < GBK; kr += 8) {                         \
            uint32_t af[2][4];                                                          \
            uint32_t bf[8][2];                                                          \
            _Pragma("unroll") for (int mt = 0; mt < 2; mt++) {                          \
                int mb = wm + mt * 16 + g;                                              \
                af[mt][0] = __float_as_uint(ap[(kr + tig) * (GBM + 4) + mb]);           \
                af[mt][1] = __float_as_uint(ap[(kr + tig) * (GBM + 4) + mb + 8]);       \
                af[mt][2] = __float_as_uint(ap[(kr + tig + 4) * (GBM + 4) + mb]);       \
                af[mt][3] = __float_as_uint(ap[(kr + tig + 4) * (GBM + 4) + mb + 8]);   \
            }                                                                           \
            _Pragma("unroll") for (int j = 0; j < 8; j++) {                             \
                int nb = wn + j * 8 + g;                                                \
                bf[j][0] = __float_as_uint(bp[(kr + tig) * (GBN + 4) + nb]);            \
                bf[j][1] = __float_as_uint(bp[(kr + tig + 4) * (GBN + 4) + nb]);        \
            }                                                                           \
            _Pragma("unroll") for (int mt = 0; mt < 2; mt++)                            \
                _Pragma("unroll") for (int j = 0; j < 8; j++)                           \
                    mma_tf32(acc[mt][j], af[mt], bf[j]);                                \
        }                                                                               \
    }

    LOAD_TILE(0);
    STORE_TILE(0);
    __syncthreads();

    int buf = 0;
#pragma unroll
    for (int t = 1; t < HID / GBK; t++) {
        LOAD_TILE(t * GBK);
        COMPUTE_TILE(buf);
        STORE_TILE(buf ^ 1);
        __syncthreads();
        buf ^= 1;
    }
    COMPUTE_TILE(buf);

#pragma unroll
    for (int mt = 0; mt < 2; mt++) {
        int row0 = bm + wm + mt * 16 + g;
        int row1 = row0 + 8;
#pragma unroll
        for (int j = 0; j < 8; j++) {
            int col = bn + wn + j * 8 + tig * 2;
            if (row0 < M)
                *(__half2*)&Ch[(size_t)row0 * HID + col] = __floats2half2_rn(acc[mt][j].x, acc[mt][j].y);
            if (row1 < M)
                *(__half2*)&Ch[(size_t)row1 * HID + col] = __floats2half2_rn(acc[mt][j].z, acc[mt][j].w);
        }
    }
#undef LOAD_TILE
#undef STORE_TILE
#undef COMPUTE_TILE
}

// ---------------- kernel 2: zero deg + cnt ----------------
__global__ void zero_kernel(float* __restrict__ deg, int* __restrict__ cnt, int N) {
    int i = blockIdx.x * blockDim.x + threadIdx.x;
    if (i < N) { deg[i] = 0.0f; cnt[i] = 0; }
}

// ---------------- kernel 3: fused edge MLP -> w, + weighted degree + histogram ----------------
__global__ __launch_bounds__(256) void fused_edge_kernel(const float* __restrict__ attr,
                                const float* __restrict__ W1,
                                const float* __restrict__ b1,
                                const float* __restrict__ W2,
                                const float* __restrict__ b2,
                                const int* __restrict__ dst,
                                float* __restrict__ w,
                                float* __restrict__ deg,
                                int* __restrict__ cnt, int E) {
    __shared__ float4 sA[128];
    __shared__ float  sV[128];
    __shared__ float  sAttr[768];
    int tid = threadIdx.x;
    if (tid < 128) {
        sA[tid] = make_float4(W1[tid], W1[128 + tid], W1[256 + tid], b1[tid]);
        sV[tid] = W2[tid];
    }
    long base3 = (long)blockIdx.x * 768;
    if (base3 + 768 <= (long)E * 3) {
        if (tid < 192)
            ((float4*)sAttr)[tid] = ((const float4*)(attr + base3))[tid];
    } else {
        for (int i = tid; i < 768; i += 256) {
            long gi = base3 + i;
            sAttr[i] = (gi < (long)E * 3) ? attr[gi] : 0.0f;
        }
    }
    __syncthreads();
    int e = blockIdx.x * blockDim.x + tid;
    if (e >= E) return;
    float a0 = sAttr[tid * 3 + 0];
    float a1 = sAttr[tid * 3 + 1];
    float a2 = sAttr[tid * 3 + 2];
    float acc = b2[0];
#pragma unroll 8
    for (int j = 0; j < 128; j++) {
        float4 c = sA[j];
        float z = fmaf(a0, c.x, fmaf(a1, c.y, fmaf(a2, c.z, c.w)));
        float t = tanh_approx(0.5f * z);
        acc = fmaf(0.5f * z * (1.0f + t), sV[j], acc);
    }
    float wv = fmaf(0.5f, tanh_approx(0.5f * acc), 0.5f);
    w[e] = wv;
    int c = dst[e];
    atomicAdd(&deg[c], wv);
    atomicAdd(&cnt[c], 1);
}

// ---------------- kernels 4a/4b/4c: 3-phase device-wide exclusive scan ----------------
__global__ __launch_bounds__(256) void scan_bsum_kernel(const int* __restrict__ cnt,
                                                        int* __restrict__ bsum, int N) {
    __shared__ int s[256];
    int t = threadIdx.x;
    int base = blockIdx.x * SCB;
    int v = 0;
    int i0 = base + t, i1 = base + t + 256;
    if (i0 < N) v += cnt[i0];
    if (i1 < N) v += cnt[i1];
    s[t] = v;
    __syncthreads();
#pragma unroll
    for (int off = 128; off > 0; off >>= 1) {
        if (t < off) s[t] += s[t + off];
        __syncthreads();
    }
    if (t == 0) bsum[blockIdx.x] = s[0];
}

__global__ __launch_bounds__(128) void scan_mid_kernel(int* __restrict__ bsum, int nb) {
    __shared__ int s[128];
    int t = threadIdx.x;
    int v = (t < nb) ? bsum[t] : 0;
    s[t] = v;
    __syncthreads();
#pragma unroll
    for (int off = 1; off < 128; off <<= 1) {
        int u = (t >= off) ? s[t - off] : 0;
        __syncthreads();
        s[t] += u;
        __syncthreads();
    }
    if (t < nb) bsum[t] = s[t] - v;     // exclusive
    if (t == 127) bsum[nb] = s[127];    // total
}

__global__ __launch_bounds__(256) void scan_final_kernel(const int* __restrict__ cnt,
                                                         const int* __restrict__ bsum,
                                                         const float* __restrict__ deg,
                                                         int* __restrict__ ptr,
                                                         int* __restrict__ cur,
                                                         float* __restrict__ dinv,
                                                         int N, int nb) {
    __shared__ int s[256];
    int t = threadIdx.x;
    int base = blockIdx.x * SCB;
    int i0 = base + 2 * t, i1 = i0 + 1;
    int p0 = (i0 < N) ? cnt[i0] : 0;
    int p1 = (i1 < N) ? cnt[i1] : 0;
    int pair = p0 + p1;
    s[t] = pair;
    __syncthreads();
#pragma unroll
    for (int off = 1; off < 256; off <<= 1) {
        int u = (t >= off) ? s[t - off] : 0;
        __syncthreads();
        s[t] += u;
        __syncthreads();
    }
    int excl = s[t] - pair + bsum[blockIdx.x];
    if (i0 < N) {
        ptr[i0] = excl; cur[i0] = excl;
        dinv[i0] = rsqrtf(deg[i0] + 1.0f);   // + self loop weight
    }
    if (i1 < N) {
        ptr[i1] = excl + p0; cur[i1] = excl + p0;
        dinv[i1] = rsqrtf(deg[i1] + 1.0f);
    }
    if (blockIdx.x == 0 && t == 0) ptr[N] = bsum[nb];
}

// ---------------- kernel 5: scatter packed (src, norm) into dst-grouped CSR ----------------
__global__ void scatter_kernel(const int* __restrict__ src,
                               const int* __restrict__ dst,
                               const float* __restrict__ w,
                               const float* __restrict__ dinv,
                               int* __restrict__ cur,
                               int2* __restrict__ epack, int E) {
    int e = blockIdx.x * blockDim.x + threadIdx.x;
    if (e >= E) return;
    int r = src[e];
    int c = dst[e];
    float nrm = w[e] * dinv[r] * dinv[c];
    int pos = atomicAdd(&cur[c], 1);
    epack[pos] = make_int2(r, __float_as_int(nrm));   // single STG.64
}

// ---------------- kernel 6: pull aggregation, 2 warps / node, ILP-4 fp16 gather ----------------
// warp-pair per node: each warp owns 128 columns; lane owns 4 halves (uint2 = 8B).
__global__ __launch_bounds__(256) void agg_pull_kernel(const int* __restrict__ ptr,
                                                       const int2* __restrict__ epack,
                                                       const float* __restrict__ dinv,
                                                       const __half* __restrict__ xh,
                                                       const float* __restrict__ bc,
                                                       float* __restrict__ out, int N) {
    int gw = (blockIdx.x * blockDim.x + threadIdx.x) >> 5;   // global warp id
    int node = gw >> 1;
    int half = gw & 1;
    int lane = threadIdx.x & 31;
    if (node >= N) return;

    const uint2* xh2 = (const uint2*)xh;      // 64 uint2 per row
    int cidx = half * 32 + lane;              // this lane's uint2/float4 index [0,64)
    size_t rowbase = (size_t)node * 64;

    float d = dinv[node];
    float s = d * d;                          // self-loop norm

    // self term (fp16 x) + bias
    uint2 sv = xh2[rowbase + cidx];
    float2 s0 = __half22float2(((const __half2*)&sv)[0]);
    float2 s1 = __half22float2(((const __half2*)&sv)[1]);
    float4 bcv = ((const float4*)bc)[cidx];
    float4 acc;
    acc.x = fmaf(s, s0.x, bcv.x);
    acc.y = fmaf(s, s0.y, bcv.y);
    acc.z = fmaf(s, s1.x, bcv.z);
    acc.w = fmaf(s, s1.y, bcv.w);

    int beg = ptr[node];
    int end = ptr[node + 1];

    for (int i0 = beg; i0 < end; i0 += 32) {
        int m = min(32, end - i0);
        int rl = 0; float nml = 0.0f;
        if (lane < m) {
            int2 pk = epack[i0 + lane];       // coalesced 8B metadata (dup across warp pair)
            rl = pk.x; nml = __int_as_float(pk.y);
        }

        int j = 0;
        for (; j + 4 <= m; j += 4) {
            int rr[4]; float nn[4];
#pragma unroll
            for (int u = 0; u < 4; u++) {
                rr[u] = __shfl_sync(0xffffffffu, rl, j + u);
                nn[u] = __shfl_sync(0xffffffffu, nml, j + u);
            }
            uint2 hv[4];
#pragma unroll
            for (int u = 0; u < 4; u++)                   // 4 independent LDG.64
                hv[u] = xh2[(size_t)rr[u] * 64 + cidx];
#pragma unroll
            for (int u = 0; u < 4; u++) {
                float nm = nn[u];
                float2 f0 = __half22float2(((const __half2*)&hv[u])[0]);
                float2 f1 = __half22float2(((const __half2*)&hv[u])[1]);
                acc.x = fmaf(nm, f0.x, acc.x);
                acc.y = fmaf(nm, f0.y, acc.y);
                acc.z = fmaf(nm, f1.x, acc.z);
                acc.w = fmaf(nm, f1.y, acc.w);
            }
        }
        for (; j < m; j++) {
            int r = __shfl_sync(0xffffffffu, rl, j);
            float nm = __shfl_sync(0xffffffffu, nml, j);
            uint2 hv = xh2[(size_t)r * 64 + cidx];
            float2 f0 = __half22float2(((const __half2*)&hv)[0]);
            float2 f1 = __half22float2(((const __half2*)&hv)[1]);
            acc.x = fmaf(nm, f0.x, acc.x);
            acc.y = fmaf(nm, f0.y, acc.y);
            acc.z = fmaf(nm, f1.x, acc.z);
            acc.w = fmaf(nm, f1.y, acc.w);
        }
    }
    ((float4*)out)[rowbase + cidx] = acc;
}

// ---------------- launcher ----------------
extern "C" void kernel_launch(void* const* d_in, const int* in_sizes, int n_in,
                              void* d_out, int out_size) {
    const float* h    = (const float*)d_in[0];
    const int*   eidx = (const int*)d_in[1];     // JAX int64 -> int32 (x64 disabled)
    const float* attr = (const float*)d_in[2];
    const float* W1   = (const float*)d_in[3];
    const float* b1   = (const float*)d_in[4];
    const float* W2   = (const float*)d_in[5];
    const float* b2   = (const float*)d_in[6];
    const float* Wc   = (const float*)d_in[7];
    const float* bc   = (const float*)d_in[8];
    float* out = (float*)d_out;

    int N = in_sizes[0] / HID;       // 50000
    int E = in_sizes[2] / 3;         // 800000
    const int* src = eidx;
    const int* dst = eidx + E;

    float*  w_dev;    cudaGetSymbolAddress((void**)&w_dev, g_w);
    float*  deg_dev;  cudaGetSymbolAddress((void**)&deg_dev, g_deg);
    float*  dinv_dev; cudaGetSymbolAddress((void**)&dinv_dev, g_dinv);
    int*    cnt_dev;  cudaGetSymbolAddress((void**)&cnt_dev, g_cnt);
    int*    ptr_dev;  cudaGetSymbolAddress((void**)&ptr_dev, g_ptr);
    int*    cur_dev;  cudaGetSymbolAddress((void**)&cur_dev, g_cur);
    int*    bsum_dev; cudaGetSymbolAddress((void**)&bsum_dev, g_bsum);
    int2*   epack_dev; cudaGetSymbolAddress((void**)&epack_dev, g_epack);
    __half* xh_dev;   cudaGetSymbolAddress((void**)&xh_dev, g_xh);

    static cudaStream_t s_side = nullptr;
    static cudaEvent_t s_fork = nullptr, s_join = nullptr;
    if (!s_side) {
        cudaStreamCreateWithFlags(&s_side, cudaStreamNonBlocking);
        cudaEventCreateWithFlags(&s_fork, cudaEventDisableTiming);
        cudaEventCreateWithFlags(&s_join, cudaEventDisableTiming);
        cudaFuncSetAttribute(tf32_gemm_kernel,
                             cudaFuncAttributeMaxDynamicSharedMemorySize, GEMM_SMEM);
    }

    int nb = (N + SCB - 1) / SCB;    // 98 scan blocks

    // fork: GEMM on side stream (pull is the only consumer of xh)
    cudaEventRecord(s_fork, 0);
    cudaStreamWaitEvent(s_side, s_fork, 0);
    dim3 ggrid((N + GBM - 1) / GBM, HID / GBN);
    tf32_gemm_kernel<<<ggrid, 256, GEMM_SMEM, s_side>>>(h, Wc, xh_dev, N);
    cudaEventRecord(s_join, s_side);

    // main stream: CSR build chain
    zero_kernel<<<(N + 255) / 256, 256>>>(deg_dev, cnt_dev, N);
    fused_edge_kernel<<<(E + 255) / 256, 256>>>(attr, W1, b1, W2, b2, dst, w_dev, deg_dev, cnt_dev, E);
    scan_bsum_kernel<<<nb, 256>>>(cnt_dev, bsum_dev, N);
    scan_mid_kernel<<<1, 128>>>(bsum_dev, nb);
    scan_final_kernel<<<nb, 256>>>(cnt_dev, bsum_dev, deg_dev, ptr_dev, cur_dev, dinv_dev, N, nb);
    scatter_kernel<<<(E + 255) / 256, 256>>>(src, dst, w_dev, dinv_dev, cur_dev, epack_dev, E);

    // join, then pull (needs xh)
    cudaStreamWaitEvent(0, s_join, 0);
    int warps = 2 * N;
    agg_pull_kernel<<<(warps * 32 + 255) / 256, 256>>>(ptr_dev, epack_dev, dinv_dev, xh_dev, bc, out, N);
}